// round 2
// baseline (speedup 1.0000x reference)
#include <cuda_runtime.h>
#include <cstdint>
#include <cstddef>

constexpr int Bn  = 512;
constexpr int QLn = 128;
constexpr int ALn = 512;
constexpr int Fn  = 400;
constexpr int Fp  = 512;
constexpr int KD2 = 912;   // 900 padded to 76*12 (75 valid chunks)
constexpr int EPL = 67;
constexpr int SMEM_CONV = (300 * EPL + 12 * 128) * 4;  // 86544 B

using ull = unsigned long long;

__device__ float d_Wflat[Fp * KD2];
__device__ float d_W2[Fp * KD2];
__device__ float d_biasPad[Fp];
__device__ float d_b2[Fp];
__device__ float d_A[(size_t)Bn * Fn * ALn];
__device__ float d_Q[(size_t)Bn * Fn * QLn];
__device__ float d_tQ[(size_t)Bn * Fn * QLn];
__device__ float d_maxQp[Bn * 4 * QLn];
__device__ float d_maxA[Bn * ALn];

__device__ __forceinline__ void fma2(ull& c, ull a, ull b) {
    asm("fma.rn.f32x2 %0, %1, %2, %0;" : "+l"(c) : "l"(a), "l"(b));
}
__device__ __forceinline__ ull bcast2(float x) {
    ull r; asm("mov.b64 %0, {%1, %1};" : "=l"(r) : "f"(x)); return r;
}
__device__ __forceinline__ float2 up2(ull v) {
    float2 r; asm("mov.b64 {%0, %1}, %2;" : "=f"(r.x), "=f"(r.y) : "l"(v)); return r;
}
__device__ __forceinline__ float tanh_fast(float x) {
    float e = __expf(2.0f * x);
    return 1.0f - __fdividef(2.0f, e + 1.0f);
}

// Wflat[f][k*300+e] = conv_w[f,e,k], zero-padded to [512][912]
__global__ void prep_w(const float* __restrict__ cw, const float* __restrict__ cb,
                       float* __restrict__ Wflat, float* __restrict__ biasPad) {
    int idx = blockIdx.x * 256 + threadIdx.x;
    if (idx < Fp) biasPad[idx] = (idx < Fn) ? cb[idx] : 0.0f;
    if (idx >= Fp * KD2) return;
    int f = idx / KD2, kk = idx - f * KD2;
    float v = 0.0f;
    if (f < Fn && kk < 900) {
        int k = kk / 300, e = kk - k * 300;
        v = cw[(f * 300 + e) * 3 + k];
    }
    Wflat[idx] = v;
}

// W2 = U^T Wflat ; b2 = U^T conv_b
__global__ void prep_w2(const float* __restrict__ U, const float* __restrict__ cb,
                        const float* __restrict__ Wflat,
                        float* __restrict__ W2, float* __restrict__ b2) {
    int idx = blockIdx.x * 256 + threadIdx.x;
    if (idx < Fp) {
        float a = 0.0f;
        if (idx < Fn) for (int f = 0; f < Fn; f++) a += U[f * Fn + idx] * cb[f];
        b2[idx] = a;
    }
    if (idx >= Fp * KD2) return;
    int g = idx / KD2, kk = idx - g * KD2;
    float a = 0.0f;
    if (g < Fn) {
#pragma unroll 4
        for (int f = 0; f < Fn; f++) a += U[f * Fn + g] * Wflat[(size_t)f * KD2 + kk];
    }
    W2[idx] = a;
}

// fused gather + conv GEMM: out[b][f][l] = bias[f] + sum_{k,e} W[f][k*300+e]*emb[tok[b,l+k-1],e]
// tile 128f x 64l, BK=12, 256 thr, per-thread 8f(x4 f32x2) x 4l
__global__ void __launch_bounds__(256, 2)
conv_kernel(const int* __restrict__ tok, int L,
            const float* __restrict__ emb, const float* __restrict__ W,
            const float* __restrict__ bias, float* __restrict__ out) {
    extern __shared__ float sm[];
    float* Et = sm;               // [300][EPL], Et[e][r], r = pos-lBase+1
    float* Ws = sm + 300 * EPL;   // [12][128]
    __shared__ int stok[66];

    const int tid = threadIdx.x;
    const int tx = tid & 15, ty = tid >> 4;
    const int lBase = blockIdx.x * 64;
    const int fBase = blockIdx.y * 128;
    const int b = blockIdx.z;

    if (tid < 66) {
        int pos = lBase + tid - 1;
        stok[tid] = (pos >= 0 && pos < L) ? tok[b * L + pos] : -1;
    }
    __syncthreads();
    for (int idx = tid; idx < 66 * 75; idx += 256) {
        int r = idx / 75, c = idx - r * 75;
        int t = stok[r];
        float4 v = make_float4(0.f, 0.f, 0.f, 0.f);
        if (t >= 0) v = *(const float4*)(emb + (size_t)t * 300 + c * 4);
        int e = c * 4;
        Et[(e + 0) * EPL + r] = v.x; Et[(e + 1) * EPL + r] = v.y;
        Et[(e + 2) * EPL + r] = v.z; Et[(e + 3) * EPL + r] = v.w;
    }

    ull acc[4][4];
#pragma unroll
    for (int i = 0; i < 4; i++)
#pragma unroll
        for (int j = 0; j < 4; j++) acc[i][j] = 0ull;

    const float* Wrow = W + (size_t)(fBase + (tid & 127)) * KD2;
    const float* wb2 = Ws + ty * 8;

    for (int kc = 0; kc < 75; kc++) {
        int kk0 = kc * 12;
        int kp = kc / 25;           // constant k within chunk (300 = 25*12)
        int e0 = kk0 - kp * 300;
        __syncthreads();
        if (tid < 128) {
            const float* wr = Wrow + kk0;
            float4 wa = *(const float4*)wr;
            float4 wb = *(const float4*)(wr + 4);
            float4 wc = *(const float4*)(wr + 8);
            float* p = Ws + tid;
            p[0]    = wa.x; p[128]  = wa.y; p[256]  = wa.z; p[384]  = wa.w;
            p[512]  = wb.x; p[640]  = wb.y; p[768]  = wb.z; p[896]  = wb.w;
            p[1024] = wc.x; p[1152] = wc.y; p[1280] = wc.z; p[1408] = wc.w;
        }
        __syncthreads();
        const float* eb = Et + e0 * EPL + tx + kp;
#pragma unroll
        for (int kk = 0; kk < 12; kk++) {
            ulonglong2 w01 = *(const ulonglong2*)(wb2 + kk * 128);
            ulonglong2 w23 = *(const ulonglong2*)(wb2 + kk * 128 + 4);
#pragma unroll
            for (int j = 0; j < 4; j++) {
                ull ev = bcast2(eb[kk * EPL + j * 16]);
                fma2(acc[0][j], w01.x, ev);
                fma2(acc[1][j], w01.y, ev);
                fma2(acc[2][j], w23.x, ev);
                fma2(acc[3][j], w23.y, ev);
            }
        }
    }

#pragma unroll
    for (int ip = 0; ip < 4; ip++) {
        int f0 = fBase + ty * 8 + ip * 2;
        if (f0 < Fn) {
            float b0 = bias[f0], b1 = bias[f0 + 1];
#pragma unroll
            for (int j = 0; j < 4; j++) {
                float2 v = up2(acc[ip][j]);
                int l = lBase + tx + j * 16;
                out[((size_t)b * Fn + f0) * L + l]     = v.x + b0;
                out[((size_t)b * Fn + f0 + 1) * L + l] = v.y + b1;
            }
        }
    }
}

// G-tile (128q x 128a) maxes; grid (4 a-tiles, B)
__global__ void __launch_bounds__(256)
g_kernel(const float* __restrict__ tQ, const float* __restrict__ A,
         float* __restrict__ maxQp, float* __restrict__ maxA) {
    __shared__ float Ts[8][128];
    __shared__ float As[8][128];
    __shared__ float red[16][129];

    const int tid = threadIdx.x;
    const int tx = tid & 15, ty = tid >> 4;
    const int at = blockIdx.x, b = blockIdx.y;

    ull acc[8][4];
#pragma unroll
    for (int i = 0; i < 8; i++)
#pragma unroll
        for (int j = 0; j < 4; j++) acc[i][j] = 0ull;

    const int r = tid >> 5, c4 = (tid & 31) * 4;
    const float* tqb = tQ + (size_t)b * Fn * QLn;
    const float* ab  = A + (size_t)b * Fn * ALn + at * 128;

    for (int kc = 0; kc < 50; kc++) {
        __syncthreads();
        *(float4*)&Ts[r][c4] = *(const float4*)(tqb + (size_t)(kc * 8 + r) * QLn + c4);
        *(float4*)&As[r][c4] = *(const float4*)(ab  + (size_t)(kc * 8 + r) * ALn + c4);
        __syncthreads();
#pragma unroll
        for (int kk = 0; kk < 8; kk++) {
            float4 t0 = *(const float4*)&Ts[kk][ty * 8];
            float4 t1 = *(const float4*)&Ts[kk][ty * 8 + 4];
            ulonglong2 a01 = *(const ulonglong2*)&As[kk][tx * 8];
            ulonglong2 a23 = *(const ulonglong2*)&As[kk][tx * 8 + 4];
            float tv[8] = {t0.x, t0.y, t0.z, t0.w, t1.x, t1.y, t1.z, t1.w};
#pragma unroll
            for (int i = 0; i < 8; i++) {
                ull tp = bcast2(tv[i]);
                fma2(acc[i][0], tp, a01.x);
                fma2(acc[i][1], tp, a01.y);
                fma2(acc[i][2], tp, a23.x);
                fma2(acc[i][3], tp, a23.y);
            }
        }
    }

    float rowm[8], colm[8];
#pragma unroll
    for (int i = 0; i < 8; i++) { rowm[i] = -2.0f; colm[i] = -2.0f; }
#pragma unroll
    for (int i = 0; i < 8; i++)
#pragma unroll
        for (int jp = 0; jp < 4; jp++) {
            float2 v = up2(acc[i][jp]);
            float g0 = tanh_fast(v.x), g1 = tanh_fast(v.y);
            rowm[i] = fmaxf(rowm[i], fmaxf(g0, g1));
            colm[2 * jp]     = fmaxf(colm[2 * jp], g0);
            colm[2 * jp + 1] = fmaxf(colm[2 * jp + 1], g1);
        }

    __syncthreads();
#pragma unroll
    for (int i = 0; i < 8; i++) red[tx][ty * 8 + i] = rowm[i];
    __syncthreads();
    if (tid < 128) {
        float m = -2.0f;
#pragma unroll
        for (int t = 0; t < 16; t++) m = fmaxf(m, red[t][tid]);
        maxQp[((size_t)b * 4 + at) * QLn + tid] = m;
    }
    __syncthreads();
#pragma unroll
    for (int j = 0; j < 8; j++) red[ty][tx * 8 + j] = colm[j];
    __syncthreads();
    if (tid < 128) {
        float m = -2.0f;
#pragma unroll
        for (int t = 0; t < 16; t++) m = fmaxf(m, red[t][tid]);
        maxA[(size_t)b * ALn + at * 128 + tid] = m;
    }
}

__device__ __forceinline__ float blkReduce(float v, bool domax) {
    __shared__ float sb[8];
#pragma unroll
    for (int o = 16; o; o >>= 1) {
        float ov = __shfl_xor_sync(0xffffffffu, v, o);
        v = domax ? fmaxf(v, ov) : v + ov;
    }
    __syncthreads();
    if ((threadIdx.x & 31) == 0) sb[threadIdx.x >> 5] = v;
    __syncthreads();
    float r = sb[0];
#pragma unroll
    for (int w = 1; w < 8; w++) r = domax ? fmaxf(r, sb[w]) : r + sb[w];
    return r;
}

__global__ void __launch_bounds__(256)
final_kernel(const float* __restrict__ Q, const float* __restrict__ A,
             const float* __restrict__ maxQp, const float* __restrict__ maxA,
             float* __restrict__ out) {
    __shared__ float roQ[QLn];
    __shared__ float roA[ALn];
    __shared__ float rQ[Fn];
    __shared__ float rA[Fn];
    const int b = blockIdx.x, tid = threadIdx.x;

    float v = -2.0f;
    if (tid < QLn) {
        const float* mp = maxQp + (size_t)b * 4 * QLn + tid;
        v = fmaxf(fmaxf(mp[0], mp[QLn]), fmaxf(mp[2 * QLn], mp[3 * QLn]));
    }
    float m = blkReduce(v, true);
    float e = (tid < QLn) ? __expf(v - m) : 0.0f;
    float s = blkReduce(e, false);
    if (tid < QLn) roQ[tid] = e / s;

    float v0 = maxA[(size_t)b * ALn + tid];
    float v1 = maxA[(size_t)b * ALn + 256 + tid];
    m = blkReduce(fmaxf(v0, v1), true);
    float e0 = __expf(v0 - m), e1 = __expf(v1 - m);
    s = blkReduce(e0 + e1, false);
    roA[tid] = e0 / s;
    roA[tid + 256] = e1 / s;
    __syncthreads();

    for (int f = tid; f < Fn; f += 256) {
        const float4* qr = (const float4*)(Q + ((size_t)b * Fn + f) * QLn);
        float a = 0.0f;
#pragma unroll 8
        for (int c = 0; c < QLn / 4; c++) {
            float4 q = qr[c];
            const float* w = &roQ[c * 4];
            a += q.x * w[0] + q.y * w[1] + q.z * w[2] + q.w * w[3];
        }
        rQ[f] = a;
    }
    for (int f = tid; f < Fn; f += 256) {
        const float4* ar = (const float4*)(A + ((size_t)b * Fn + f) * ALn);
        float a = 0.0f;
#pragma unroll 8
        for (int c = 0; c < ALn / 4; c++) {
            float4 q = ar[c];
            const float* w = &roA[c * 4];
            a += q.x * w[0] + q.y * w[1] + q.z * w[2] + q.w * w[3];
        }
        rA[f] = a;
    }
    __syncthreads();

    float d = 0.0f, qq = 0.0f, aa = 0.0f;
    for (int f = tid; f < Fn; f += 256) {
        float x = rQ[f], y = rA[f];
        d += x * y; qq += x * x; aa += y * y;
    }
    d = blkReduce(d, false);
    qq = blkReduce(qq, false);
    aa = blkReduce(aa, false);
    if (tid == 0)
        out[b] = d / (fmaxf(sqrtf(qq), 1e-8f) * fmaxf(sqrtf(aa), 1e-8f));
}

extern "C" void kernel_launch(void* const* d_in, const int* in_sizes, int n_in,
                              void* d_out, int out_size) {
    const int*   question = (const int*)d_in[0];
    const int*   answer   = (const int*)d_in[1];
    const float* emb      = (const float*)d_in[2];
    const float* conv_w   = (const float*)d_in[3];
    const float* conv_b   = (const float*)d_in[4];
    const float* U        = (const float*)d_in[5];
    float* out = (float*)d_out;

    float *Wflat, *W2, *biasPad, *b2, *Ac, *Qc, *tQc, *maxQp, *maxA;
    cudaGetSymbolAddress((void**)&Wflat,   d_Wflat);
    cudaGetSymbolAddress((void**)&W2,      d_W2);
    cudaGetSymbolAddress((void**)&biasPad, d_biasPad);
    cudaGetSymbolAddress((void**)&b2,      d_b2);
    cudaGetSymbolAddress((void**)&Ac,      d_A);
    cudaGetSymbolAddress((void**)&Qc,      d_Q);
    cudaGetSymbolAddress((void**)&tQc,     d_tQ);
    cudaGetSymbolAddress((void**)&maxQp,   d_maxQp);
    cudaGetSymbolAddress((void**)&maxA,    d_maxA);

    cudaFuncSetAttribute(conv_kernel, cudaFuncAttributeMaxDynamicSharedMemorySize, SMEM_CONV);

    const int prepBlocks = (Fp * KD2) / 256;
    prep_w<<<prepBlocks, 256>>>(conv_w, conv_b, Wflat, biasPad);
    prep_w2<<<prepBlocks, 256>>>(U, conv_b, Wflat, W2, b2);

    dim3 gA(ALn / 64, Fp / 128, Bn);
    conv_kernel<<<gA, 256, SMEM_CONV>>>(answer, ALn, emb, Wflat, biasPad, Ac);
    dim3 gQ(QLn / 64, Fp / 128, Bn);
    conv_kernel<<<gQ, 256, SMEM_CONV>>>(question, QLn, emb, Wflat, biasPad, Qc);
    conv_kernel<<<gQ, 256, SMEM_CONV>>>(question, QLn, emb, W2, b2, tQc);

    dim3 gG(4, Bn);
    g_kernel<<<gG, 256>>>(tQc, Ac, maxQp, maxA);
    final_kernel<<<Bn, 256>>>(Qc, Ac, maxQp, maxA, out);
}

// round 4
// speedup vs baseline: 1.7125x; 1.7125x over previous
#include <cuda_runtime.h>
#include <cuda_bf16.h>
#include <cstdint>
#include <cstddef>

constexpr int Bn  = 512;
constexpr int QLn = 128;
constexpr int ALn = 512;
constexpr int Fn  = 400;
constexpr int Fp  = 512;
constexpr int KDp = 960;                 // 900 padded to 15*64
constexpr int NEMB = 50001 * 300;
constexpr int STR = 137;                 // smem row stride in u32 (conflict-free fill)
constexpr int TILE_U32 = 32 * STR;       // 4384 u32 per tile
constexpr int SMEM_MMA = 4 * TILE_U32 * 4;  // 70144 B

using ull = unsigned long long;

// ---------------- device scratch ----------------
__device__ float d_Wflat[Fp * KDp];
__device__ float d_biasPad[Fp];
__device__ float d_b2[Fp];
__device__ __nv_bfloat16 d_Whi[Fp * KDp];
__device__ __nv_bfloat16 d_Wlo[Fp * KDp];
__device__ __nv_bfloat16 d_W2hi[Fp * KDp];
__device__ __nv_bfloat16 d_W2lo[Fp * KDp];
__device__ __nv_bfloat16 d_embHi[NEMB];
__device__ __nv_bfloat16 d_embLo[NEMB];
__device__ float d_A[(size_t)Bn * Fn * ALn];
__device__ float d_Q[(size_t)Bn * Fn * QLn];
__device__ float d_tQ[(size_t)Bn * Fn * QLn];
__device__ float d_maxQp[Bn * 4 * QLn];
__device__ float d_maxA[Bn * ALn];

// ---------------- helpers ----------------
__device__ __forceinline__ void fma2(ull& c, ull a, ull b) {
    asm("fma.rn.f32x2 %0, %1, %2, %0;" : "+l"(c) : "l"(a), "l"(b));
}
__device__ __forceinline__ ull bcast2(float x) {
    ull r; asm("mov.b64 %0, {%1, %1};" : "=l"(r) : "f"(x)); return r;
}
__device__ __forceinline__ float2 up2(ull v) {
    float2 r; asm("mov.b64 {%0, %1}, %2;" : "=f"(r.x), "=f"(r.y) : "l"(v)); return r;
}
__device__ __forceinline__ float tanh_fast(float x) {
    float e = __expf(2.0f * x);
    return 1.0f - __fdividef(2.0f, e + 1.0f);
}
__device__ __forceinline__ void mma_bf16(float* c, const uint32_t* a, uint32_t b0, uint32_t b1) {
    asm volatile(
        "mma.sync.aligned.m16n8k16.row.col.f32.bf16.bf16.f32 "
        "{%0,%1,%2,%3}, {%4,%5,%6,%7}, {%8,%9}, {%0,%1,%2,%3};"
        : "+f"(c[0]), "+f"(c[1]), "+f"(c[2]), "+f"(c[3])
        : "r"(a[0]), "r"(a[1]), "r"(a[2]), "r"(a[3]), "r"(b0), "r"(b1));
}

// ---------------- prep kernels ----------------
__global__ void prep_w(const float* __restrict__ cw, const float* __restrict__ cb,
                       float* __restrict__ Wflat, float* __restrict__ biasPad,
                       __nv_bfloat16* __restrict__ Whi, __nv_bfloat16* __restrict__ Wlo) {
    int idx = blockIdx.x * 256 + threadIdx.x;
    if (idx < Fp) biasPad[idx] = (idx < Fn) ? cb[idx] : 0.0f;
    if (idx >= Fp * KDp) return;
    int f = idx / KDp, kk = idx - f * KDp;
    float v = 0.0f;
    if (f < Fn && kk < 900) {
        int k = kk / 300, e = kk - k * 300;
        v = cw[(f * 300 + e) * 3 + k];
    }
    Wflat[idx] = v;
    __nv_bfloat16 h = __float2bfloat16(v);
    Whi[idx] = h;
    Wlo[idx] = __float2bfloat16(v - __bfloat162float(h));
}

__global__ void prep_w2(const float* __restrict__ U, const float* __restrict__ cb,
                        const float* __restrict__ Wflat, float* __restrict__ b2,
                        __nv_bfloat16* __restrict__ W2hi, __nv_bfloat16* __restrict__ W2lo) {
    int idx = blockIdx.x * 256 + threadIdx.x;
    if (idx < Fp) {
        float a = 0.0f;
        if (idx < Fn) for (int f = 0; f < Fn; f++) a += U[f * Fn + idx] * cb[f];
        b2[idx] = a;
    }
    if (idx >= Fp * KDp) return;
    int g = idx / KDp, kk = idx - g * KDp;
    float a = 0.0f;
    if (g < Fn && kk < 900) {
#pragma unroll 4
        for (int f = 0; f < Fn; f++) a += U[f * Fn + g] * Wflat[(size_t)f * KDp + kk];
    }
    __nv_bfloat16 h = __float2bfloat16(a);
    W2hi[idx] = h;
    W2lo[idx] = __float2bfloat16(a - __bfloat162float(h));
}

__global__ void emb_cvt(const float* __restrict__ emb, int n,
                        __nv_bfloat16* __restrict__ hi, __nv_bfloat16* __restrict__ lo) {
    int idx = blockIdx.x * 256 + threadIdx.x;
    if (idx >= n) return;
    float v = emb[idx];
    __nv_bfloat16 h = __float2bfloat16(v);
    hi[idx] = h;
    lo[idx] = __float2bfloat16(v - __bfloat162float(h));
}

// ---------------- HMMA conv GEMM ----------------
// D[128f x 128l] = W[128x960] * X[960x128l], bf16 hi/lo 3-pass, fp32 accum.
// smem tiles: [32 k2-rows][STR=137 u32] per tile (u32 = bf16 pair along k).
__global__ void __launch_bounds__(256, 2)
conv_mma(const int* __restrict__ tok, int L,
         const __nv_bfloat16* __restrict__ eHi, const __nv_bfloat16* __restrict__ eLo,
         const __nv_bfloat16* __restrict__ wHi, const __nv_bfloat16* __restrict__ wLo,
         const float* __restrict__ bias, float* __restrict__ out) {
    extern __shared__ uint32_t sm4[];
    uint32_t* sWh = sm4;
    uint32_t* sWl = sm4 + TILE_U32;
    uint32_t* sXh = sm4 + 2 * TILE_U32;
    uint32_t* sXl = sm4 + 3 * TILE_U32;
    __shared__ int stok[132];

    const int tid = threadIdx.x;
    const int wid = tid >> 5;
    const int lane = tid & 31;
    const int r = lane & 3, q = lane >> 2;
    const int wmf = wid & 3;          // f-quadrant (32 f each)
    const int wnf = wid >> 2;         // l-half (64 l each)
    const int lBase = blockIdx.x * 128;
    const int fBase = blockIdx.y * 128;
    const int b = blockIdx.z;

    if (tid < 130) {
        int pos = lBase + tid - 1;
        stok[tid] = (pos >= 0 && pos < L) ? tok[b * L + pos] : -1;
    }

    float acc[2][8][4];
#pragma unroll
    for (int mt = 0; mt < 2; mt++)
#pragma unroll
        for (int nt = 0; nt < 8; nt++)
#pragma unroll
            for (int i = 0; i < 4; i++) acc[mt][nt][i] = 0.0f;

    const __nv_bfloat16* wHrow = wHi + (size_t)fBase * KDp;
    const __nv_bfloat16* wLrow = wLo + (size_t)fBase * KDp;

    for (int s = 0; s < 15; s++) {
        __syncthreads();
        // fill W tiles: warp handles f = it*8 + wid (const per warp), c2 = lane
#pragma unroll
        for (int it = 0; it < 16; it++) {
            int f = it * 8 + wid;
            int c2 = lane;
            size_t g = (size_t)f * KDp + s * 64 + c2 * 2;
            sWh[c2 * STR + f] = *(const uint32_t*)(wHrow + g);
            sWl[c2 * STR + f] = *(const uint32_t*)(wLrow + g);
        }
        // fill X tiles: l = it*8 + wid, c2 = lane; kk = s*64 + 2*c2
#pragma unroll
        for (int it = 0; it < 16; it++) {
            int l = it * 8 + wid;
            int c2 = lane;
            int kk = s * 64 + c2 * 2;
            uint32_t vh = 0u, vl = 0u;
            if (kk < 900) {
                int k = (kk < 300) ? 0 : (kk < 600) ? 1 : 2;
                int t = stok[l + k];
                if (t >= 0) {
                    size_t g = (size_t)t * 300 + (kk - k * 300);
                    vh = *(const uint32_t*)(eHi + g);
                    vl = *(const uint32_t*)(eLo + g);
                }
            }
            sXh[c2 * STR + l] = vh;
            sXl[c2 * STR + l] = vl;
        }
        __syncthreads();

#pragma unroll
        for (int kt = 0; kt < 4; kt++) {
            const uint32_t* wh = sWh + (kt * 8 + r) * STR + q + wmf * 32;
            const uint32_t* wl = sWl + (kt * 8 + r) * STR + q + wmf * 32;
            const uint32_t* xh = sXh + (kt * 8 + r) * STR + q + wnf * 64;
            const uint32_t* xl = sXl + (kt * 8 + r) * STR + q + wnf * 64;
            uint32_t ah[8], al[8];
#pragma unroll
            for (int mt = 0; mt < 2; mt++) {
                ah[mt * 4 + 0] = wh[mt * 16];
                ah[mt * 4 + 1] = wh[mt * 16 + 8];
                ah[mt * 4 + 2] = wh[4 * STR + mt * 16];
                ah[mt * 4 + 3] = wh[4 * STR + mt * 16 + 8];
                al[mt * 4 + 0] = wl[mt * 16];
                al[mt * 4 + 1] = wl[mt * 16 + 8];
                al[mt * 4 + 2] = wl[4 * STR + mt * 16];
                al[mt * 4 + 3] = wl[4 * STR + mt * 16 + 8];
            }
#pragma unroll
            for (int nt = 0; nt < 8; nt++) {
                uint32_t bh0 = xh[nt * 8];
                uint32_t bh1 = xh[4 * STR + nt * 8];
                uint32_t bl0 = xl[nt * 8];
                uint32_t bl1 = xl[4 * STR + nt * 8];
                mma_bf16(acc[0][nt], ah,     bh0, bh1);   // hi*hi
                mma_bf16(acc[1][nt], ah + 4, bh0, bh1);
                mma_bf16(acc[0][nt], ah,     bl0, bl1);   // hi*lo
                mma_bf16(acc[1][nt], ah + 4, bl0, bl1);
                mma_bf16(acc[0][nt], al,     bh0, bh1);   // lo*hi
                mma_bf16(acc[1][nt], al + 4, bh0, bh1);
            }
        }
    }

    // epilogue: c0,c1 at (f = base + q, l = l0 + 2r), c2,c3 at f+8
#pragma unroll
    for (int mt = 0; mt < 2; mt++) {
        int f0 = fBase + wmf * 32 + mt * 16 + q;
        float bv0 = (f0 < Fn) ? bias[f0] : 0.0f;
        float bv1 = (f0 + 8 < Fn) ? bias[f0 + 8] : 0.0f;
#pragma unroll
        for (int nt = 0; nt < 8; nt++) {
            int l = lBase + wnf * 64 + nt * 8 + r * 2;
            if (f0 < Fn) {
                float2 v = make_float2(acc[mt][nt][0] + bv0, acc[mt][nt][1] + bv0);
                *(float2*)(out + ((size_t)b * Fn + f0) * L + l) = v;
            }
            if (f0 + 8 < Fn) {
                float2 v = make_float2(acc[mt][nt][2] + bv1, acc[mt][nt][3] + bv1);
                *(float2*)(out + ((size_t)b * Fn + f0 + 8) * L + l) = v;
            }
        }
    }
}

// ---------------- G-tile maxes (CUDA cores) ----------------
__global__ void __launch_bounds__(256)
g_kernel(const float* __restrict__ tQ, const float* __restrict__ A,
         float* __restrict__ maxQp, float* __restrict__ maxA) {
    __shared__ float Ts[8][128];
    __shared__ float As[8][128];
    __shared__ float red[16][129];

    const int tid = threadIdx.x;
    const int tx = tid & 15, ty = tid >> 4;
    const int at = blockIdx.x, b = blockIdx.y;

    ull acc[8][4];
#pragma unroll
    for (int i = 0; i < 8; i++)
#pragma unroll
        for (int j = 0; j < 4; j++) acc[i][j] = 0ull;

    const int r = tid >> 5, c4 = (tid & 31) * 4;
    const float* tqb = tQ + (size_t)b * Fn * QLn;
    const float* ab  = A + (size_t)b * Fn * ALn + at * 128;

    for (int kc = 0; kc < 50; kc++) {
        __syncthreads();
        *(float4*)&Ts[r][c4] = *(const float4*)(tqb + (size_t)(kc * 8 + r) * QLn + c4);
        *(float4*)&As[r][c4] = *(const float4*)(ab  + (size_t)(kc * 8 + r) * ALn + c4);
        __syncthreads();
#pragma unroll
        for (int kk = 0; kk < 8; kk++) {
            float4 t0 = *(const float4*)&Ts[kk][ty * 8];
            float4 t1 = *(const float4*)&Ts[kk][ty * 8 + 4];
            ulonglong2 a01 = *(const ulonglong2*)&As[kk][tx * 8];
            ulonglong2 a23 = *(const ulonglong2*)&As[kk][tx * 8 + 4];
            float tv[8] = {t0.x, t0.y, t0.z, t0.w, t1.x, t1.y, t1.z, t1.w};
#pragma unroll
            for (int i = 0; i < 8; i++) {
                ull tp = bcast2(tv[i]);
                fma2(acc[i][0], tp, a01.x);
                fma2(acc[i][1], tp, a01.y);
                fma2(acc[i][2], tp, a23.x);
                fma2(acc[i][3], tp, a23.y);
            }
        }
    }

    float rowm[8], colm[8];
#pragma unroll
    for (int i = 0; i < 8; i++) { rowm[i] = -2.0f; colm[i] = -2.0f; }
#pragma unroll
    for (int i = 0; i < 8; i++)
#pragma unroll
        for (int jp = 0; jp < 4; jp++) {
            float2 v = up2(acc[i][jp]);
            float g0 = tanh_fast(v.x), g1 = tanh_fast(v.y);
            rowm[i] = fmaxf(rowm[i], fmaxf(g0, g1));
            colm[2 * jp]     = fmaxf(colm[2 * jp], g0);
            colm[2 * jp + 1] = fmaxf(colm[2 * jp + 1], g1);
        }

    __syncthreads();
#pragma unroll
    for (int i = 0; i < 8; i++) red[tx][ty * 8 + i] = rowm[i];
    __syncthreads();
    if (tid < 128) {
        float m = -2.0f;
#pragma unroll
        for (int t = 0; t < 16; t++) m = fmaxf(m, red[t][tid]);
        maxQp[((size_t)b * 4 + at) * QLn + tid] = m;
    }
    __syncthreads();
#pragma unroll
    for (int j = 0; j < 8; j++) red[ty][tx * 8 + j] = colm[j];
    __syncthreads();
    if (tid < 128) {
        float m = -2.0f;
#pragma unroll
        for (int t = 0; t < 16; t++) m = fmaxf(m, red[t][tid]);
        maxA[(size_t)b * ALn + at * 128 + tid] = m;
    }
}

__device__ __forceinline__ float blkReduce(float v, bool domax) {
    __shared__ float sb[8];
#pragma unroll
    for (int o = 16; o; o >>= 1) {
        float ov = __shfl_xor_sync(0xffffffffu, v, o);
        v = domax ? fmaxf(v, ov) : v + ov;
    }
    __syncthreads();
    if ((threadIdx.x & 31) == 0) sb[threadIdx.x >> 5] = v;
    __syncthreads();
    float r = sb[0];
#pragma unroll
    for (int w = 1; w < 8; w++) r = domax ? fmaxf(r, sb[w]) : r + sb[w];
    return r;
}

__global__ void __launch_bounds__(256)
final_kernel(const float* __restrict__ Q, const float* __restrict__ A,
             const float* __restrict__ maxQp, const float* __restrict__ maxA,
             float* __restrict__ out) {
    __shared__ float roQ[QLn];
    __shared__ float roA[ALn];
    __shared__ float rQ[Fn];
    __shared__ float rA[Fn];
    const int b = blockIdx.x, tid = threadIdx.x;

    float v = -2.0f;
    if (tid < QLn) {
        const float* mp = maxQp + (size_t)b * 4 * QLn + tid;
        v = fmaxf(fmaxf(mp[0], mp[QLn]), fmaxf(mp[2 * QLn], mp[3 * QLn]));
    }
    float m = blkReduce(v, true);
    float e = (tid < QLn) ? __expf(v - m) : 0.0f;
    float s = blkReduce(e, false);
    if (tid < QLn) roQ[tid] = e / s;

    float v0 = maxA[(size_t)b * ALn + tid];
    float v1 = maxA[(size_t)b * ALn + 256 + tid];
    m = blkReduce(fmaxf(v0, v1), true);
    float e0 = __expf(v0 - m), e1 = __expf(v1 - m);
    s = blkReduce(e0 + e1, false);
    roA[tid] = e0 / s;
    roA[tid + 256] = e1 / s;
    __syncthreads();

    for (int f = tid; f < Fn; f += 256) {
        const float4* qr = (const float4*)(Q + ((size_t)b * Fn + f) * QLn);
        float a = 0.0f;
#pragma unroll 8
        for (int c = 0; c < QLn / 4; c++) {
            float4 qv = qr[c];
            const float* w = &roQ[c * 4];
            a += qv.x * w[0] + qv.y * w[1] + qv.z * w[2] + qv.w * w[3];
        }
        rQ[f] = a;
    }
    for (int f = tid; f < Fn; f += 256) {
        const float4* ar = (const float4*)(A + ((size_t)b * Fn + f) * ALn);
        float a = 0.0f;
#pragma unroll 8
        for (int c = 0; c < ALn / 4; c++) {
            float4 qv = ar[c];
            const float* w = &roA[c * 4];
            a += qv.x * w[0] + qv.y * w[1] + qv.z * w[2] + qv.w * w[3];
        }
        rA[f] = a;
    }
    __syncthreads();

    float d = 0.0f, qq = 0.0f, aa = 0.0f;
    for (int f = tid; f < Fn; f += 256) {
        float x = rQ[f], y = rA[f];
        d += x * y; qq += x * x; aa += y * y;
    }
    d = blkReduce(d, false);
    qq = blkReduce(qq, false);
    aa = blkReduce(aa, false);
    if (tid == 0)
        out[b] = d / (fmaxf(sqrtf(qq), 1e-8f) * fmaxf(sqrtf(aa), 1e-8f));
}

// ---------------- launch ----------------
extern "C" void kernel_launch(void* const* d_in, const int* in_sizes, int n_in,
                              void* d_out, int out_size) {
    const int*   question = (const int*)d_in[0];
    const int*   answer   = (const int*)d_in[1];
    const float* emb      = (const float*)d_in[2];
    const float* conv_w   = (const float*)d_in[3];
    const float* conv_b   = (const float*)d_in[4];
    const float* U        = (const float*)d_in[5];
    float* out = (float*)d_out;

    float *Wflat, *biasPad, *b2, *Ac, *Qc, *tQc, *maxQp, *maxA;
    __nv_bfloat16 *Whi, *Wlo, *W2hi, *W2lo, *eHi, *eLo;
    cudaGetSymbolAddress((void**)&Wflat,   d_Wflat);
    cudaGetSymbolAddress((void**)&biasPad, d_biasPad);
    cudaGetSymbolAddress((void**)&b2,      d_b2);
    cudaGetSymbolAddress((void**)&Whi,     d_Whi);
    cudaGetSymbolAddress((void**)&Wlo,     d_Wlo);
    cudaGetSymbolAddress((void**)&W2hi,    d_W2hi);
    cudaGetSymbolAddress((void**)&W2lo,    d_W2lo);
    cudaGetSymbolAddress((void**)&eHi,     d_embHi);
    cudaGetSymbolAddress((void**)&eLo,     d_embLo);
    cudaGetSymbolAddress((void**)&Ac,      d_A);
    cudaGetSymbolAddress((void**)&Qc,      d_Q);
    cudaGetSymbolAddress((void**)&tQc,     d_tQ);
    cudaGetSymbolAddress((void**)&maxQp,   d_maxQp);
    cudaGetSymbolAddress((void**)&maxA,    d_maxA);

    cudaFuncSetAttribute(conv_mma, cudaFuncAttributeMaxDynamicSharedMemorySize, SMEM_MMA);

    const int prepBlocks = (Fp * KDp) / 256;  // 1920
    prep_w<<<prepBlocks, 256>>>(conv_w, conv_b, Wflat, biasPad, Whi, Wlo);
    prep_w2<<<prepBlocks, 256>>>(U, conv_b, Wflat, b2, W2hi, W2lo);
    int nEmb = in_sizes[2];
    emb_cvt<<<(nEmb + 255) / 256, 256>>>(emb, nEmb, eHi, eLo);

    dim3 gA(ALn / 128, Fp / 128, Bn);
    conv_mma<<<gA, 256, SMEM_MMA>>>(answer, ALn, eHi, eLo, Whi, Wlo, biasPad, Ac);
    dim3 gQ(QLn / 128, Fp / 128, Bn);
    conv_mma<<<gQ, 256, SMEM_MMA>>>(question, QLn, eHi, eLo, Whi, Wlo, biasPad, Qc);
    conv_mma<<<gQ, 256, SMEM_MMA>>>(question, QLn, eHi, eLo, W2hi, W2lo, b2, tQc);

    dim3 gG(4, Bn);
    g_kernel<<<gG, 256>>>(tQc, Ac, maxQp, maxA);
    final_kernel<<<Bn, 256>>>(Qc, Ac, maxQp, maxA, out);
}

// round 6
// speedup vs baseline: 2.4280x; 1.4178x over previous
#include <cuda_runtime.h>
#include <cuda_bf16.h>
#include <cstdint>
#include <cstddef>

constexpr int Bn  = 512;
constexpr int QLn = 128;
constexpr int ALn = 512;
constexpr int Fn  = 400;
constexpr int Fp  = 512;
constexpr int EPW = 304;                 // e padded to 19*16 (also emb row stride!)
constexpr int NS  = 19;                  // pipeline stages
constexpr int NEMBP = 50001 * EPW;       // padded embedding elements
constexpr int STAGE_B = 33024;           // (768 W rows + 264 X rows) * 32B
constexpr int SMEM_MMA = 2 * STAGE_B;    // 66048 B

using ull = unsigned long long;

// ---------------- device scratch ----------------
__device__ __align__(256) float d_biasPad[Fp];
__device__ __align__(256) float d_b2[Fp];
__device__ __align__(256) __nv_bfloat16 d_Whi[3 * Fp * EPW];
__device__ __align__(256) __nv_bfloat16 d_Wlo[3 * Fp * EPW];
__device__ __align__(256) __nv_bfloat16 d_W2hi[3 * Fp * EPW];
__device__ __align__(256) __nv_bfloat16 d_W2lo[3 * Fp * EPW];
__device__ __align__(256) __nv_bfloat16 d_embHi[NEMBP];
__device__ __align__(256) __nv_bfloat16 d_embLo[NEMBP];
__device__ __align__(256) float d_A[(size_t)Bn * Fn * ALn];
__device__ __align__(256) float d_Q[(size_t)Bn * Fn * QLn];
__device__ __align__(256) float d_tQ[(size_t)Bn * Fn * QLn];
__device__ __align__(256) float d_maxQp[Bn * 4 * QLn];
__device__ __align__(256) float d_maxA[Bn * ALn];

// ---------------- helpers ----------------
__device__ __forceinline__ void fma2(ull& c, ull a, ull b) {
    asm("fma.rn.f32x2 %0, %1, %2, %0;" : "+l"(c) : "l"(a), "l"(b));
}
__device__ __forceinline__ ull bcast2(float x) {
    ull r; asm("mov.b64 %0, {%1, %1};" : "=l"(r) : "f"(x)); return r;
}
__device__ __forceinline__ float2 up2(ull v) {
    float2 r; asm("mov.b64 {%0, %1}, %2;" : "=f"(r.x), "=f"(r.y) : "l"(v)); return r;
}
__device__ __forceinline__ float tanh_fast(float x) {
    float e = __expf(2.0f * x);
    return 1.0f - __fdividef(2.0f, e + 1.0f);
}
__device__ __forceinline__ uint32_t smem_u32(const void* p) {
    uint32_t a;
    asm("{ .reg .u64 t; cvta.to.shared.u64 t, %1; cvt.u32.u64 %0, t; }" : "=r"(a) : "l"(p));
    return a;
}
__device__ __forceinline__ void mma_bf16(float* c, const uint32_t* a, uint32_t b0, uint32_t b1) {
    asm volatile(
        "mma.sync.aligned.m16n8k16.row.col.f32.bf16.bf16.f32 "
        "{%0,%1,%2,%3}, {%4,%5,%6,%7}, {%8,%9}, {%0,%1,%2,%3};"
        : "+f"(c[0]), "+f"(c[1]), "+f"(c[2]), "+f"(c[3])
        : "r"(a[0]), "r"(a[1]), "r"(a[2]), "r"(a[3]), "r"(b0), "r"(b1));
}
__device__ __forceinline__ void ldsm4(uint32_t* r, uint32_t addr) {
    asm volatile("ldmatrix.sync.aligned.m8n8.x4.shared.b16 {%0,%1,%2,%3}, [%4];"
        : "=r"(r[0]), "=r"(r[1]), "=r"(r[2]), "=r"(r[3]) : "r"(addr));
}
__device__ __forceinline__ void cp16(uint32_t dst, const void* src, uint32_t sz) {
    asm volatile("cp.async.cg.shared.global [%0], [%1], 16, %2;"
        :: "r"(dst), "l"(src), "r"(sz) : "memory");
}
// row-major tiles of 32B rows (2x16B chunks), chunk XOR swizzle -> conflict-free ldmatrix
__device__ __forceinline__ uint32_t swaddr(uint32_t base, uint32_t row, uint32_t chunk) {
    return base + row * 32u + ((chunk ^ ((row >> 2) & 1u)) << 4);
}

// ---------------- prep kernels ----------------
// Whi/Wlo[j][f][e] = split(conv_w[f,e,j]), zero-padded
__global__ void prep_w(const float* __restrict__ cw, const float* __restrict__ cb,
                       float* __restrict__ biasPad,
                       __nv_bfloat16* __restrict__ Whi, __nv_bfloat16* __restrict__ Wlo) {
    int idx = blockIdx.x * 256 + threadIdx.x;
    if (idx < Fp) biasPad[idx] = (idx < Fn) ? cb[idx] : 0.0f;
    if (idx >= 3 * Fp * EPW) return;
    int j = idx / (Fp * EPW), rem = idx - j * (Fp * EPW);
    int f = rem / EPW, e = rem - f * EPW;
    float v = 0.0f;
    if (f < Fn && e < 300) v = cw[(f * 300 + e) * 3 + j];
    __nv_bfloat16 h = __float2bfloat16(v);
    Whi[idx] = h;
    Wlo[idx] = __float2bfloat16(v - __bfloat162float(h));
}

// W2[j][g][e] = sum_f U[f][g] * conv_w[f,e,j];  b2 = U^T conv_b
__global__ void prep_w2(const float* __restrict__ U, const float* __restrict__ cb,
                        const float* __restrict__ cw, float* __restrict__ b2,
                        __nv_bfloat16* __restrict__ W2hi, __nv_bfloat16* __restrict__ W2lo) {
    int idx = blockIdx.x * 256 + threadIdx.x;
    if (idx < Fp) {
        float a = 0.0f;
        if (idx < Fn) for (int f = 0; f < Fn; f++) a += U[f * Fn + idx] * cb[f];
        b2[idx] = a;
    }
    if (idx >= 3 * Fp * EPW) return;
    int j = idx / (Fp * EPW), rem = idx - j * (Fp * EPW);
    int g = rem / EPW, e = rem - g * EPW;
    float a = 0.0f;
    if (g < Fn && e < 300) {
#pragma unroll 4
        for (int f = 0; f < Fn; f++) a += U[f * Fn + g] * cw[(f * 300 + e) * 3 + j];
    }
    __nv_bfloat16 h = __float2bfloat16(a);
    W2hi[idx] = h;
    W2lo[idx] = __float2bfloat16(a - __bfloat162float(h));
}

// padded split: hi/lo[t*304 + e] = split(emb[t*300 + e]) (e<300), else 0
__global__ void emb_cvt(const float* __restrict__ emb,
                        __nv_bfloat16* __restrict__ hi, __nv_bfloat16* __restrict__ lo) {
    int idx = blockIdx.x * 256 + threadIdx.x;
    if (idx >= NEMBP) return;
    int t = idx / EPW, e = idx - t * EPW;
    float v = (e < 300) ? emb[(size_t)t * 300 + e] : 0.0f;
    __nv_bfloat16 h = __float2bfloat16(v);
    hi[idx] = h;
    lo[idx] = __float2bfloat16(v - __bfloat162float(h));
}

// ---------------- pipelined HMMA conv GEMM ----------------
// Out[b][f][l] = bias[f] + sum_j sum_e W[j][f][e] * emb[tok[b][l+j-1]][e]
// Stage = e-chunk of 16. Per stage smem:
//   rows 0..767:    W[j2 = j*2+tbl][f] (32B rows = 16 bf16)
//   rows 768..1031: X[tbl][r] (r = pos - lBase + 1, 130 valid + 2 pad)
__device__ __forceinline__ void fill_stage(
    uint32_t stage, int s, int tid, int fBase,
    const __nv_bfloat16* __restrict__ wH, const __nv_bfloat16* __restrict__ wL,
    const __nv_bfloat16* __restrict__ eH, const __nv_bfloat16* __restrict__ eL,
    const int* stok) {
    const int e0 = s * 16;
    // W: 1536 16B chunks
#pragma unroll
    for (int it = 0; it < 6; it++) {
        int idx = it * 256 + tid;
        uint32_t row = (uint32_t)idx >> 1, chunk = idx & 1;
        uint32_t j2 = row >> 7, f = row & 127u;
        const __nv_bfloat16* src = ((j2 & 1) ? wL : wH)
            + ((size_t)(j2 >> 1) * Fp + fBase + f) * EPW + e0 + chunk * 8;
        cp16(swaddr(stage, row, chunk), src, 16u);
    }
    // X: 520 16B chunks (130 rows x 2 tables x 2 chunks); emb rows padded to EPW -> 16B aligned
#pragma unroll
    for (int it = 0; it < 3; it++) {
        int idx = it * 256 + tid;
        if (idx < 520) {
            uint32_t tbl = (idx >= 260) ? 1u : 0u;
            uint32_t rem = idx - tbl * 260;
            uint32_t r = rem >> 1, chunk = rem & 1;
            int t = stok[r];
            const __nv_bfloat16* src = (tbl ? eL : eH)
                + (size_t)(t < 0 ? 0 : t) * EPW + e0 + chunk * 8;
            cp16(swaddr(stage, 768u + tbl * 132u + r, chunk), src, (t < 0) ? 0u : 16u);
        }
    }
}

__global__ void __launch_bounds__(256, 2)
conv_mma(const int* __restrict__ tok, int L,
         const __nv_bfloat16* __restrict__ eH, const __nv_bfloat16* __restrict__ eL,
         const __nv_bfloat16* __restrict__ wH, const __nv_bfloat16* __restrict__ wL,
         const float* __restrict__ bias, float* __restrict__ out) {
    extern __shared__ uint32_t dsm[];
    __shared__ int stok[132];

    const int tid = threadIdx.x;
    const int wid = tid >> 5;
    const int lane = tid & 31;
    const int wmf = wid & 3;          // f-quadrant (32 f each)
    const int wnf = wid >> 2;         // l-half (64 l each)
    const int r4 = lane & 3, q = lane >> 2;
    const int lBase = blockIdx.x * 128;
    const int fBase = blockIdx.y * 128;
    const int b = blockIdx.z;

    const uint32_t sbase = smem_u32(dsm);

    if (tid < 130) {
        int pos = lBase + tid - 1;
        stok[tid] = (pos >= 0 && pos < L) ? tok[b * L + pos] : -1;
    }
    __syncthreads();

    float acc[2][8][4];
#pragma unroll
    for (int mt = 0; mt < 2; mt++)
#pragma unroll
        for (int nt = 0; nt < 8; nt++)
#pragma unroll
            for (int i = 0; i < 4; i++) acc[mt][nt][i] = 0.0f;

    fill_stage(sbase, 0, tid, fBase, wH, wL, eH, eL, stok);
    asm volatile("cp.async.commit_group;" ::: "memory");

    for (int s = 0; s < NS; s++) {
        if (s + 1 < NS)
            fill_stage(sbase + (uint32_t)((s + 1) & 1) * STAGE_B, s + 1, tid, fBase, wH, wL, eH, eL, stok);
        asm volatile("cp.async.commit_group;" ::: "memory");
        asm volatile("cp.async.wait_group 1;" ::: "memory");
        __syncthreads();

        const uint32_t stg = sbase + (uint32_t)(s & 1) * STAGE_B;
#pragma unroll
        for (int j = 0; j < 3; j++) {
            uint32_t ah[8], al[8], bf[16];
            // A fragments: rows = j*256 + tbl*128 + f
            uint32_t rowA = (uint32_t)(j * 256) + (uint32_t)(wmf * 32)
                          + (((uint32_t)lane >> 3) & 1u) * 8u + ((uint32_t)lane & 7u);
            uint32_t aaddr = swaddr(stg, rowA, (uint32_t)lane >> 4);
            ldsm4(ah, aaddr);            // f 0-15 of quad (hi)
            ldsm4(ah + 4, aaddr + 512);  // f 16-31 (hi)
            ldsm4(al, aaddr + 4096);     // lo table (+128 rows)
            ldsm4(al + 4, aaddr + 4096 + 512);
            // B fragments: rows = 768 + tbl*132 + l_local + j
            uint32_t rowB = 768u + (uint32_t)(wnf * 64) + (((uint32_t)lane >> 4) << 3)
                          + ((uint32_t)lane & 7u) + (uint32_t)j;
            uint32_t chB = ((uint32_t)lane >> 3) & 1u;
            uint32_t baddrH = swaddr(stg, rowB, chB);
            uint32_t baddrL = swaddr(stg, rowB + 132u, chB);
            ldsm4(bf, baddrH); ldsm4(bf + 4, baddrH + 512);
            ldsm4(bf + 8, baddrH + 1024); ldsm4(bf + 12, baddrH + 1536);
#pragma unroll
            for (int nt = 0; nt < 8; nt++) {
                mma_bf16(acc[0][nt], ah,     bf[2 * nt], bf[2 * nt + 1]);  // hi*hi
                mma_bf16(acc[1][nt], ah + 4, bf[2 * nt], bf[2 * nt + 1]);
                mma_bf16(acc[0][nt], al,     bf[2 * nt], bf[2 * nt + 1]);  // lo*hi
                mma_bf16(acc[1][nt], al + 4, bf[2 * nt], bf[2 * nt + 1]);
            }
            ldsm4(bf, baddrL); ldsm4(bf + 4, baddrL + 512);
            ldsm4(bf + 8, baddrL + 1024); ldsm4(bf + 12, baddrL + 1536);
#pragma unroll
            for (int nt = 0; nt < 8; nt++) {
                mma_bf16(acc[0][nt], ah,     bf[2 * nt], bf[2 * nt + 1]);  // hi*lo
                mma_bf16(acc[1][nt], ah + 4, bf[2 * nt], bf[2 * nt + 1]);
            }
        }
        __syncthreads();
    }

    // epilogue: c0,c1 at (f = fq + mt*16 + q, l = l0 + nt*8 + 2*r4), c2,c3 at f+8
#pragma unroll
    for (int mt = 0; mt < 2; mt++) {
        int f0 = fBase + wmf * 32 + mt * 16 + q;
        float bv0 = (f0 < Fn) ? bias[f0] : 0.0f;
        float bv1 = (f0 + 8 < Fn) ? bias[f0 + 8] : 0.0f;
#pragma unroll
        for (int nt = 0; nt < 8; nt++) {
            int l = lBase + wnf * 64 + nt * 8 + r4 * 2;
            if (f0 < Fn) {
                float2 v = make_float2(acc[mt][nt][0] + bv0, acc[mt][nt][1] + bv0);
                *(float2*)(out + ((size_t)b * Fn + f0) * L + l) = v;
            }
            if (f0 + 8 < Fn) {
                float2 v = make_float2(acc[mt][nt][2] + bv1, acc[mt][nt][3] + bv1);
                *(float2*)(out + ((size_t)b * Fn + f0 + 8) * L + l) = v;
            }
        }
    }
}

// ---------------- G-tile maxes (CUDA cores) ----------------
__global__ void __launch_bounds__(256)
g_kernel(const float* __restrict__ tQ, const float* __restrict__ A,
         float* __restrict__ maxQp, float* __restrict__ maxA) {
    __shared__ float Ts[8][128];
    __shared__ float As[8][128];
    __shared__ float red[16][129];

    const int tid = threadIdx.x;
    const int tx = tid & 15, ty = tid >> 4;
    const int at = blockIdx.x, b = blockIdx.y;

    ull acc[8][4];
#pragma unroll
    for (int i = 0; i < 8; i++)
#pragma unroll
        for (int j = 0; j < 4; j++) acc[i][j] = 0ull;

    const int r = tid >> 5, c4 = (tid & 31) * 4;
    const float* tqb = tQ + (size_t)b * Fn * QLn;
    const float* ab  = A + (size_t)b * Fn * ALn + at * 128;

    for (int kc = 0; kc < 50; kc++) {
        __syncthreads();
        *(float4*)&Ts[r][c4] = *(const float4*)(tqb + (size_t)(kc * 8 + r) * QLn + c4);
        *(float4*)&As[r][c4] = *(const float4*)(ab  + (size_t)(kc * 8 + r) * ALn + c4);
        __syncthreads();
#pragma unroll
        for (int kk = 0; kk < 8; kk++) {
            float4 t0 = *(const float4*)&Ts[kk][ty * 8];
            float4 t1 = *(const float4*)&Ts[kk][ty * 8 + 4];
            ulonglong2 a01 = *(const ulonglong2*)&As[kk][tx * 8];
            ulonglong2 a23 = *(const ulonglong2*)&As[kk][tx * 8 + 4];
            float tv[8] = {t0.x, t0.y, t0.z, t0.w, t1.x, t1.y, t1.z, t1.w};
#pragma unroll
            for (int i = 0; i < 8; i++) {
                ull tp = bcast2(tv[i]);
                fma2(acc[i][0], tp, a01.x);
                fma2(acc[i][1], tp, a01.y);
                fma2(acc[i][2], tp, a23.x);
                fma2(acc[i][3], tp, a23.y);
            }
        }
    }

    float rowm[8], colm[8];
#pragma unroll
    for (int i = 0; i < 8; i++) { rowm[i] = -2.0f; colm[i] = -2.0f; }
#pragma unroll
    for (int i = 0; i < 8; i++)
#pragma unroll
        for (int jp = 0; jp < 4; jp++) {
            float2 v = up2(acc[i][jp]);
            float g0 = tanh_fast(v.x), g1 = tanh_fast(v.y);
            rowm[i] = fmaxf(rowm[i], fmaxf(g0, g1));
            colm[2 * jp]     = fmaxf(colm[2 * jp], g0);
            colm[2 * jp + 1] = fmaxf(colm[2 * jp + 1], g1);
        }

    __syncthreads();
#pragma unroll
    for (int i = 0; i < 8; i++) red[tx][ty * 8 + i] = rowm[i];
    __syncthreads();
    if (tid < 128) {
        float m = -2.0f;
#pragma unroll
        for (int t = 0; t < 16; t++) m = fmaxf(m, red[t][tid]);
        maxQp[((size_t)b * 4 + at) * QLn + tid] = m;
    }
    __syncthreads();
#pragma unroll
    for (int j = 0; j < 8; j++) red[ty][tx * 8 + j] = colm[j];
    __syncthreads();
    if (tid < 128) {
        float m = -2.0f;
#pragma unroll
        for (int t = 0; t < 16; t++) m = fmaxf(m, red[t][tid]);
        maxA[(size_t)b * ALn + at * 128 + tid] = m;
    }
}

__device__ __forceinline__ float blkReduce(float v, bool domax) {
    __shared__ float sb[8];
#pragma unroll
    for (int o = 16; o; o >>= 1) {
        float ov = __shfl_xor_sync(0xffffffffu, v, o);
        v = domax ? fmaxf(v, ov) : v + ov;
    }
    __syncthreads();
    if ((threadIdx.x & 31) == 0) sb[threadIdx.x >> 5] = v;
    __syncthreads();
    float r = sb[0];
#pragma unroll
    for (int w = 1; w < 8; w++) r = domax ? fmaxf(r, sb[w]) : r + sb[w];
    return r;
}

__global__ void __launch_bounds__(256)
final_kernel(const float* __restrict__ Q, const float* __restrict__ A,
             const float* __restrict__ maxQp, const float* __restrict__ maxA,
             float* __restrict__ out) {
    __shared__ float roQ[QLn];
    __shared__ float roA[ALn];
    __shared__ float rQ[Fn];
    __shared__ float rA[Fn];
    const int b = blockIdx.x, tid = threadIdx.x;

    float v = -2.0f;
    if (tid < QLn) {
        const float* mp = maxQp + (size_t)b * 4 * QLn + tid;
        v = fmaxf(fmaxf(mp[0], mp[QLn]), fmaxf(mp[2 * QLn], mp[3 * QLn]));
    }
    float m = blkReduce(v, true);
    float e = (tid < QLn) ? __expf(v - m) : 0.0f;
    float s = blkReduce(e, false);
    if (tid < QLn) roQ[tid] = e / s;

    float v0 = maxA[(size_t)b * ALn + tid];
    float v1 = maxA[(size_t)b * ALn + 256 + tid];
    m = blkReduce(fmaxf(v0, v1), true);
    float e0 = __expf(v0 - m), e1 = __expf(v1 - m);
    s = blkReduce(e0 + e1, false);
    roA[tid] = e0 / s;
    roA[tid + 256] = e1 / s;
    __syncthreads();

    for (int f = tid; f < Fn; f += 256) {
        const float4* qr = (const float4*)(Q + ((size_t)b * Fn + f) * QLn);
        float a = 0.0f;
#pragma unroll 8
        for (int c = 0; c < QLn / 4; c++) {
            float4 qv = qr[c];
            const float* w = &roQ[c * 4];
            a += qv.x * w[0] + qv.y * w[1] + qv.z * w[2] + qv.w * w[3];
        }
        rQ[f] = a;
    }
    for (int f = tid; f < Fn; f += 256) {
        const float4* ar = (const float4*)(A + ((size_t)b * Fn + f) * ALn);
        float a = 0.0f;
#pragma unroll 8
        for (int c = 0; c < ALn / 4; c++) {
            float4 qv = ar[c];
            const float* w = &roA[c * 4];
            a += qv.x * w[0] + qv.y * w[1] + qv.z * w[2] + qv.w * w[3];
        }
        rA[f] = a;
    }
    __syncthreads();

    float d = 0.0f, qq = 0.0f, aa = 0.0f;
    for (int f = tid; f < Fn; f += 256) {
        float x = rQ[f], y = rA[f];
        d += x * y; qq += x * x; aa += y * y;
    }
    d = blkReduce(d, false);
    qq = blkReduce(qq, false);
    aa = blkReduce(aa, false);
    if (tid == 0)
        out[b] = d / (fmaxf(sqrtf(qq), 1e-8f) * fmaxf(sqrtf(aa), 1e-8f));
}

// ---------------- launch ----------------
extern "C" void kernel_launch(void* const* d_in, const int* in_sizes, int n_in,
                              void* d_out, int out_size) {
    const int*   question = (const int*)d_in[0];
    const int*   answer   = (const int*)d_in[1];
    const float* emb      = (const float*)d_in[2];
    const float* conv_w   = (const float*)d_in[3];
    const float* conv_b   = (const float*)d_in[4];
    const float* U        = (const float*)d_in[5];
    float* out = (float*)d_out;

    float *biasPad, *b2, *Ac, *Qc, *tQc, *maxQp, *maxA;
    __nv_bfloat16 *Whi, *Wlo, *W2hi, *W2lo, *eHi, *eLo;
    cudaGetSymbolAddress((void**)&biasPad, d_biasPad);
    cudaGetSymbolAddress((void**)&b2,      d_b2);
    cudaGetSymbolAddress((void**)&Whi,     d_Whi);
    cudaGetSymbolAddress((void**)&Wlo,     d_Wlo);
    cudaGetSymbolAddress((void**)&W2hi,    d_W2hi);
    cudaGetSymbolAddress((void**)&W2lo,    d_W2lo);
    cudaGetSymbolAddress((void**)&eHi,     d_embHi);
    cudaGetSymbolAddress((void**)&eLo,     d_embLo);
    cudaGetSymbolAddress((void**)&Ac,      d_A);
    cudaGetSymbolAddress((void**)&Qc,      d_Q);
    cudaGetSymbolAddress((void**)&tQc,     d_tQ);
    cudaGetSymbolAddress((void**)&maxQp,   d_maxQp);
    cudaGetSymbolAddress((void**)&maxA,    d_maxA);

    cudaFuncSetAttribute(conv_mma, cudaFuncAttributeMaxDynamicSharedMemorySize, SMEM_MMA);

    const int prepBlocks = (3 * Fp * EPW + 255) / 256;
    prep_w<<<prepBlocks, 256>>>(conv_w, conv_b, biasPad, Whi, Wlo);
    prep_w2<<<prepBlocks, 256>>>(U, conv_b, conv_w, b2, W2hi, W2lo);
    emb_cvt<<<(NEMBP + 255) / 256, 256>>>(emb, eHi, eLo);

    dim3 gA(ALn / 128, Fp / 128, Bn);
    conv_mma<<<gA, 256, SMEM_MMA>>>(answer, ALn, eHi, eLo, Whi, Wlo, biasPad, Ac);
    dim3 gQ(QLn / 128, Fp / 128, Bn);
    conv_mma<<<gQ, 256, SMEM_MMA>>>(question, QLn, eHi, eLo, Whi, Wlo, biasPad, Qc);
    conv_mma<<<gQ, 256, SMEM_MMA>>>(question, QLn, eHi, eLo, W2hi, W2lo, b2, tQc);

    dim3 gG(4, Bn);
    g_kernel<<<gG, 256>>>(tQc, Ac, maxQp, maxA);
    final_kernel<<<Bn, 256>>>(Qc, Ac, maxQp, maxA, out);
}

// round 7
// speedup vs baseline: 2.7683x; 1.1402x over previous
#include <cuda_runtime.h>
#include <cuda_bf16.h>
#include <cstdint>
#include <cstddef>

constexpr int Bn  = 512;
constexpr int QLn = 128;
constexpr int ALn = 512;
constexpr int Fn  = 400;
constexpr int Fp  = 512;
constexpr int EPW = 304;                 // e padded to 19*16 (also emb row stride)
constexpr int NS  = 19;                  // conv pipeline stages
constexpr int NEMBP = 50001 * EPW;
constexpr int STAGE_B = 33024;           // (768 W rows + 264 X rows) * 32B
constexpr int NBUF = 3;
constexpr int SMEM_MMA = NBUF * STAGE_B; // 99072 B

using ull = unsigned long long;

// ---------------- device scratch ----------------
__device__ __align__(256) float d_biasPad[Fp];
__device__ __align__(256) float d_b2[Fp];
__device__ __align__(256) __nv_bfloat16 d_Whi[3 * Fp * EPW];
__device__ __align__(256) __nv_bfloat16 d_Wlo[3 * Fp * EPW];
__device__ __align__(256) __nv_bfloat16 d_W2hi[3 * Fp * EPW];
__device__ __align__(256) __nv_bfloat16 d_W2lo[3 * Fp * EPW];
__device__ __align__(256) __nv_bfloat16 d_embHi[NEMBP];
__device__ __align__(256) __nv_bfloat16 d_embLo[NEMBP];
__device__ __align__(256) float d_A[(size_t)Bn * Fn * ALn];
__device__ __align__(256) float d_Q[(size_t)Bn * Fn * QLn];
__device__ __align__(256) float d_tQ[(size_t)Bn * Fn * QLn];
__device__ __align__(256) float d_maxQp[Bn * 4 * QLn];
__device__ __align__(256) float d_maxA[Bn * ALn];

// ---------------- helpers ----------------
__device__ __forceinline__ float tanh_fast(float x) {
    float e = __expf(2.0f * x);
    return 1.0f - __fdividef(2.0f, e + 1.0f);
}
__device__ __forceinline__ uint32_t smem_u32(const void* p) {
    uint32_t a;
    asm("{ .reg .u64 t; cvta.to.shared.u64 t, %1; cvt.u32.u64 %0, t; }" : "=r"(a) : "l"(p));
    return a;
}
__device__ __forceinline__ void mma_bf16(float* c, const uint32_t* a, uint32_t b0, uint32_t b1) {
    asm volatile(
        "mma.sync.aligned.m16n8k16.row.col.f32.bf16.bf16.f32 "
        "{%0,%1,%2,%3}, {%4,%5,%6,%7}, {%8,%9}, {%0,%1,%2,%3};"
        : "+f"(c[0]), "+f"(c[1]), "+f"(c[2]), "+f"(c[3])
        : "r"(a[0]), "r"(a[1]), "r"(a[2]), "r"(a[3]), "r"(b0), "r"(b1));
}
__device__ __forceinline__ void ldsm4(uint32_t* r, uint32_t addr) {
    asm volatile("ldmatrix.sync.aligned.m8n8.x4.shared.b16 {%0,%1,%2,%3}, [%4];"
        : "=r"(r[0]), "=r"(r[1]), "=r"(r[2]), "=r"(r[3]) : "r"(addr));
}
__device__ __forceinline__ void cp16(uint32_t dst, const void* src, uint32_t sz) {
    asm volatile("cp.async.cg.shared.global [%0], [%1], 16, %2;"
        :: "r"(dst), "l"(src), "r"(sz) : "memory");
}
__device__ __forceinline__ void sts128(uint32_t addr, uint32_t w0, uint32_t w1,
                                       uint32_t w2, uint32_t w3) {
    asm volatile("st.shared.v4.b32 [%0], {%1,%2,%3,%4};"
        :: "r"(addr), "r"(w0), "r"(w1), "r"(w2), "r"(w3));
}
// row-major tiles of 32B rows (2x16B chunks), chunk XOR swizzle -> conflict-free ldmatrix
__device__ __forceinline__ uint32_t swaddr(uint32_t base, uint32_t row, uint32_t chunk) {
    return base + row * 32u + ((chunk ^ ((row >> 2) & 1u)) << 4);
}
// split fp32 pair -> hi bf16x2 word (returned) and lo bf16x2 word (out param)
__device__ __forceinline__ uint32_t packsplit(float v0, float v1, uint32_t& low) {
    __nv_bfloat16 h0 = __float2bfloat16(v0), h1 = __float2bfloat16(v1);
    float l0 = v0 - __bfloat162float(h0);
    float l1 = v1 - __bfloat162float(h1);
    __nv_bfloat16 g0 = __float2bfloat16(l0), g1 = __float2bfloat16(l1);
    uint16_t a0, a1, b0, b1;
    memcpy(&a0, &h0, 2); memcpy(&a1, &h1, 2);
    memcpy(&b0, &g0, 2); memcpy(&b1, &g1, 2);
    low = (uint32_t)b0 | ((uint32_t)b1 << 16);
    return (uint32_t)a0 | ((uint32_t)a1 << 16);
}

// ---------------- prep kernels ----------------
__global__ void prep_w(const float* __restrict__ cw, const float* __restrict__ cb,
                       float* __restrict__ biasPad,
                       __nv_bfloat16* __restrict__ Whi, __nv_bfloat16* __restrict__ Wlo) {
    int idx = blockIdx.x * 256 + threadIdx.x;
    if (idx < Fp) biasPad[idx] = (idx < Fn) ? cb[idx] : 0.0f;
    if (idx >= 3 * Fp * EPW) return;
    int j = idx / (Fp * EPW), rem = idx - j * (Fp * EPW);
    int f = rem / EPW, e = rem - f * EPW;
    float v = 0.0f;
    if (f < Fn && e < 300) v = cw[(f * 300 + e) * 3 + j];
    __nv_bfloat16 h = __float2bfloat16(v);
    Whi[idx] = h;
    Wlo[idx] = __float2bfloat16(v - __bfloat162float(h));
}

__global__ void prep_w2(const float* __restrict__ U, const float* __restrict__ cb,
                        const float* __restrict__ cw, float* __restrict__ b2,
                        __nv_bfloat16* __restrict__ W2hi, __nv_bfloat16* __restrict__ W2lo) {
    int idx = blockIdx.x * 256 + threadIdx.x;
    if (idx < Fp) {
        float a = 0.0f;
        if (idx < Fn) for (int f = 0; f < Fn; f++) a += U[f * Fn + idx] * cb[f];
        b2[idx] = a;
    }
    if (idx >= 3 * Fp * EPW) return;
    int j = idx / (Fp * EPW), rem = idx - j * (Fp * EPW);
    int g = rem / EPW, e = rem - g * EPW;
    float a = 0.0f;
    if (g < Fn && e < 300) {
#pragma unroll 4
        for (int f = 0; f < Fn; f++) a += U[f * Fn + g] * cw[(f * 300 + e) * 3 + j];
    }
    __nv_bfloat16 h = __float2bfloat16(a);
    W2hi[idx] = h;
    W2lo[idx] = __float2bfloat16(a - __bfloat162float(h));
}

__global__ void emb_cvt(const float* __restrict__ emb,
                        __nv_bfloat16* __restrict__ hi, __nv_bfloat16* __restrict__ lo) {
    int idx = blockIdx.x * 256 + threadIdx.x;
    if (idx >= NEMBP) return;
    int t = idx / EPW, e = idx - t * EPW;
    float v = (e < 300) ? emb[(size_t)t * 300 + e] : 0.0f;
    __nv_bfloat16 h = __float2bfloat16(v);
    hi[idx] = h;
    lo[idx] = __float2bfloat16(v - __bfloat162float(h));
}

// ---------------- pipelined HMMA conv GEMM ----------------
__device__ __forceinline__ void fill_stage(
    uint32_t stage, int s, int tid, int fBase,
    const __nv_bfloat16* __restrict__ wH, const __nv_bfloat16* __restrict__ wL,
    const __nv_bfloat16* __restrict__ eH, const __nv_bfloat16* __restrict__ eL,
    const int* stok) {
    const int e0 = s * 16;
    // W: 1536 16B chunks; zero-fill rows with f >= Fn
#pragma unroll
    for (int it = 0; it < 6; it++) {
        int idx = it * 256 + tid;
        uint32_t row = (uint32_t)idx >> 1, chunk = idx & 1;
        uint32_t j2 = row >> 7, f = row & 127u;
        const __nv_bfloat16* src = ((j2 & 1) ? wL : wH)
            + ((size_t)(j2 >> 1) * Fp + fBase + f) * EPW + e0 + chunk * 8;
        cp16(swaddr(stage, row, chunk), src, (fBase + (int)f < Fn) ? 16u : 0u);
    }
    // X: 520 16B chunks (130 rows x 2 tables x 2 chunks)
#pragma unroll
    for (int it = 0; it < 3; it++) {
        int idx = it * 256 + tid;
        if (idx < 520) {
            uint32_t tbl = (idx >= 260) ? 1u : 0u;
            uint32_t rem = idx - tbl * 260;
            uint32_t r = rem >> 1, chunk = rem & 1;
            int t = stok[r];
            const __nv_bfloat16* src = (tbl ? eL : eH)
                + (size_t)(t < 0 ? 0 : t) * EPW + e0 + chunk * 8;
            cp16(swaddr(stage, 768u + tbl * 132u + r, chunk), src, (t < 0) ? 0u : 16u);
        }
    }
}

__global__ void __launch_bounds__(256, 2)
conv_mma(const int* __restrict__ tok, int L,
         const __nv_bfloat16* __restrict__ eH, const __nv_bfloat16* __restrict__ eL,
         const __nv_bfloat16* __restrict__ wH, const __nv_bfloat16* __restrict__ wL,
         const float* __restrict__ bias, float* __restrict__ out) {
    extern __shared__ uint32_t dsm[];
    __shared__ int stok[132];

    const int tid = threadIdx.x;
    const int wid = tid >> 5;
    const int lane = tid & 31;
    const int wmf = wid & 3;
    const int wnf = wid >> 2;
    const int r4 = lane & 3, q = lane >> 2;
    const int lBase = blockIdx.x * 128;
    const int fBase = blockIdx.y * 128;
    const int b = blockIdx.z;
    const bool fvalid = (fBase + wmf * 32) < Fn;   // whole-quadrant validity

    const uint32_t sbase = smem_u32(dsm);

    if (tid < 130) {
        int pos = lBase + tid - 1;
        stok[tid] = (pos >= 0 && pos < L) ? tok[b * L + pos] : -1;
    }
    __syncthreads();

    float acc[2][8][4];
#pragma unroll
    for (int mt = 0; mt < 2; mt++)
#pragma unroll
        for (int nt = 0; nt < 8; nt++)
#pragma unroll
            for (int i = 0; i < 4; i++) acc[mt][nt][i] = 0.0f;

    fill_stage(sbase, 0, tid, fBase, wH, wL, eH, eL, stok);
    asm volatile("cp.async.commit_group;" ::: "memory");
    fill_stage(sbase + STAGE_B, 1, tid, fBase, wH, wL, eH, eL, stok);
    asm volatile("cp.async.commit_group;" ::: "memory");

    for (int s = 0; s < NS; s++) {
        asm volatile("cp.async.wait_group 1;" ::: "memory");
        __syncthreads();
        if (s + 2 < NS)
            fill_stage(sbase + (uint32_t)((s + 2) % NBUF) * STAGE_B, s + 2,
                       tid, fBase, wH, wL, eH, eL, stok);
        asm volatile("cp.async.commit_group;" ::: "memory");

        const uint32_t stg = sbase + (uint32_t)(s % NBUF) * STAGE_B;
        if (fvalid) {
#pragma unroll
            for (int j = 0; j < 3; j++) {
                uint32_t ah[8], al[8], bf[16];
                uint32_t rowA = (uint32_t)(j * 256) + (uint32_t)(wmf * 32)
                              + (((uint32_t)lane >> 3) & 1u) * 8u + ((uint32_t)lane & 7u);
                uint32_t aaddr = swaddr(stg, rowA, (uint32_t)lane >> 4);
                ldsm4(ah, aaddr);
                ldsm4(ah + 4, aaddr + 512);
                ldsm4(al, aaddr + 4096);
                ldsm4(al + 4, aaddr + 4096 + 512);
                uint32_t rowB = 768u + (uint32_t)(wnf * 64) + (((uint32_t)lane >> 4) << 3)
                              + ((uint32_t)lane & 7u) + (uint32_t)j;
                uint32_t chB = ((uint32_t)lane >> 3) & 1u;
                uint32_t baddrH = swaddr(stg, rowB, chB);
                uint32_t baddrL = swaddr(stg, rowB + 132u, chB);
                ldsm4(bf, baddrH); ldsm4(bf + 4, baddrH + 512);
                ldsm4(bf + 8, baddrH + 1024); ldsm4(bf + 12, baddrH + 1536);
#pragma unroll
                for (int nt = 0; nt < 8; nt++) {
                    mma_bf16(acc[0][nt], ah,     bf[2 * nt], bf[2 * nt + 1]);  // hi*hi
                    mma_bf16(acc[1][nt], ah + 4, bf[2 * nt], bf[2 * nt + 1]);
                    mma_bf16(acc[0][nt], al,     bf[2 * nt], bf[2 * nt + 1]);  // lo*hi
                    mma_bf16(acc[1][nt], al + 4, bf[2 * nt], bf[2 * nt + 1]);
                }
                ldsm4(bf, baddrL); ldsm4(bf + 4, baddrL + 512);
                ldsm4(bf + 8, baddrL + 1024); ldsm4(bf + 12, baddrL + 1536);
#pragma unroll
                for (int nt = 0; nt < 8; nt++) {
                    mma_bf16(acc[0][nt], ah,     bf[2 * nt], bf[2 * nt + 1]);  // hi*lo
                    mma_bf16(acc[1][nt], ah + 4, bf[2 * nt], bf[2 * nt + 1]);
                }
            }
        }
    }

#pragma unroll
    for (int mt = 0; mt < 2; mt++) {
        int f0 = fBase + wmf * 32 + mt * 16 + q;
        float bv0 = (f0 < Fn) ? bias[f0] : 0.0f;
        float bv1 = (f0 + 8 < Fn) ? bias[f0 + 8] : 0.0f;
#pragma unroll
        for (int nt = 0; nt < 8; nt++) {
            int l = lBase + wnf * 64 + nt * 8 + r4 * 2;
            if (f0 < Fn) {
                float2 v = make_float2(acc[mt][nt][0] + bv0, acc[mt][nt][1] + bv0);
                *(float2*)(out + ((size_t)b * Fn + f0) * L + l) = v;
            }
            if (f0 + 8 < Fn) {
                float2 v = make_float2(acc[mt][nt][2] + bv1, acc[mt][nt][3] + bv1);
                *(float2*)(out + ((size_t)b * Fn + f0 + 8) * L + l) = v;
            }
        }
    }
}

// ---------------- HMMA G-tile kernel ----------------
// G[128q x 128a] = sum_f tQ[f][q]*A[f][a], K = 400 = 25 stages of 16.
// In-kernel fp32 -> bf16 hi/lo split; same swizzled tile format as conv.
// smem rows: tQhi 0-127, tQlo 128-255, Ahi 256-383, Alo 384-511 (32B rows).
__global__ void __launch_bounds__(256)
g_mma(const float* __restrict__ tQ, const float* __restrict__ A,
      float* __restrict__ maxQp, float* __restrict__ maxA) {
    __shared__ __align__(16) uint32_t stg[4096];  // 16 KB stage
    __shared__ float sRow[2][128];
    __shared__ float sCol[4][128];

    const int tid = threadIdx.x;
    const int wid = tid >> 5, lane = tid & 31;
    const int wmf = wid & 3, wnf = wid >> 2;
    const int r4 = lane & 3, q8 = lane >> 2;
    const int at = blockIdx.x, b = blockIdx.y;

    const float* tqb = tQ + (size_t)b * Fn * QLn;
    const float* ab  = A  + (size_t)b * Fn * ALn + at * 128;
    const int role = tid >> 7;          // 0: stage tQ row, 1: stage A row
    const int rrow = tid & 127;
    const float* src = role ? (ab + rrow) : (tqb + rrow);
    const int sstr = role ? ALn : QLn;
    const uint32_t sb = smem_u32(stg);

    float acc[2][8][4];
#pragma unroll
    for (int mt = 0; mt < 2; mt++)
#pragma unroll
        for (int nt = 0; nt < 8; nt++)
#pragma unroll
            for (int i = 0; i < 4; i++) acc[mt][nt][i] = 0.0f;

    float v[16];
#pragma unroll
    for (int i = 0; i < 16; i++) v[i] = src[(size_t)i * sstr];

    for (int s = 0; s < 25; s++) {
        uint32_t hw[8], lw[8];
#pragma unroll
        for (int c = 0; c < 8; c++) hw[c] = packsplit(v[2 * c], v[2 * c + 1], lw[c]);
        uint32_t rowS = (uint32_t)(role * 256 + rrow);
        sts128(swaddr(sb, rowS, 0), hw[0], hw[1], hw[2], hw[3]);
        sts128(swaddr(sb, rowS, 1), hw[4], hw[5], hw[6], hw[7]);
        sts128(swaddr(sb, rowS + 128u, 0), lw[0], lw[1], lw[2], lw[3]);
        sts128(swaddr(sb, rowS + 128u, 1), lw[4], lw[5], lw[6], lw[7]);
        __syncthreads();
        if (s < 24) {
            const float* s2 = src + (size_t)(s + 1) * 16 * sstr;
#pragma unroll
            for (int i = 0; i < 16; i++) v[i] = s2[(size_t)i * sstr];
        }
        // compute (identical fragment pattern to conv, j = 0)
        uint32_t ah[8], al[8], bfr[16];
        uint32_t rowA = (uint32_t)(wmf * 32) + (((uint32_t)lane >> 3) & 1u) * 8u
                      + ((uint32_t)lane & 7u);
        uint32_t aaddr = swaddr(sb, rowA, (uint32_t)lane >> 4);
        ldsm4(ah, aaddr); ldsm4(ah + 4, aaddr + 512);
        ldsm4(al, aaddr + 4096); ldsm4(al + 4, aaddr + 4096 + 512);
        uint32_t rowB = 256u + (uint32_t)(wnf * 64) + (((uint32_t)lane >> 4) << 3)
                      + ((uint32_t)lane & 7u);
        uint32_t chB = ((uint32_t)lane >> 3) & 1u;
        uint32_t baddrH = swaddr(sb, rowB, chB);
        uint32_t baddrL = baddrH + 4096u;  // +128 rows, same swizzle parity
        ldsm4(bfr, baddrH); ldsm4(bfr + 4, baddrH + 512);
        ldsm4(bfr + 8, baddrH + 1024); ldsm4(bfr + 12, baddrH + 1536);
#pragma unroll
        for (int nt = 0; nt < 8; nt++) {
            mma_bf16(acc[0][nt], ah,     bfr[2 * nt], bfr[2 * nt + 1]);
            mma_bf16(acc[1][nt], ah + 4, bfr[2 * nt], bfr[2 * nt + 1]);
            mma_bf16(acc[0][nt], al,     bfr[2 * nt], bfr[2 * nt + 1]);
            mma_bf16(acc[1][nt], al + 4, bfr[2 * nt], bfr[2 * nt + 1]);
        }
        ldsm4(bfr, baddrL); ldsm4(bfr + 4, baddrL + 512);
        ldsm4(bfr + 8, baddrL + 1024); ldsm4(bfr + 12, baddrL + 1536);
#pragma unroll
        for (int nt = 0; nt < 8; nt++) {
            mma_bf16(acc[0][nt], ah,     bfr[2 * nt], bfr[2 * nt + 1]);
            mma_bf16(acc[1][nt], ah + 4, bfr[2 * nt], bfr[2 * nt + 1]);
        }
        __syncthreads();
    }

    // tanh + row/col maxes.
    // value (mt,nt,ci) at q = wmf*32 + mt*16 + (ci>>1)*8 + q8, a = wnf*64 + nt*8 + r4*2 + (ci&1)
#pragma unroll
    for (int mt = 0; mt < 2; mt++)
#pragma unroll
        for (int nt = 0; nt < 8; nt++)
#pragma unroll
            for (int ci = 0; ci < 4; ci++)
                acc[mt][nt][ci] = tanh_fast(acc[mt][nt][ci]);

    float rm[4] = {-2.f, -2.f, -2.f, -2.f};   // [mt*2 + h]
    float cm[16];                              // [nt*2 + c]
#pragma unroll
    for (int i = 0; i < 16; i++) cm[i] = -2.f;
#pragma unroll
    for (int mt = 0; mt < 2; mt++)
#pragma unroll
        for (int nt = 0; nt < 8; nt++)
#pragma unroll
            for (int ci = 0; ci < 4; ci++) {
                float g = acc[mt][nt][ci];
                rm[mt * 2 + (ci >> 1)] = fmaxf(rm[mt * 2 + (ci >> 1)], g);
                cm[nt * 2 + (ci & 1)] = fmaxf(cm[nt * 2 + (ci & 1)], g);
            }
#pragma unroll
    for (int k = 0; k < 4; k++) {
        rm[k] = fmaxf(rm[k], __shfl_xor_sync(0xffffffffu, rm[k], 1));
        rm[k] = fmaxf(rm[k], __shfl_xor_sync(0xffffffffu, rm[k], 2));
    }
#pragma unroll
    for (int k = 0; k < 16; k++) {
        cm[k] = fmaxf(cm[k], __shfl_xor_sync(0xffffffffu, cm[k], 4));
        cm[k] = fmaxf(cm[k], __shfl_xor_sync(0xffffffffu, cm[k], 8));
        cm[k] = fmaxf(cm[k], __shfl_xor_sync(0xffffffffu, cm[k], 16));
    }
    if (r4 == 0) {
#pragma unroll
        for (int mt = 0; mt < 2; mt++)
#pragma unroll
            for (int h = 0; h < 2; h++)
                sRow[wnf][wmf * 32 + mt * 16 + h * 8 + q8] = rm[mt * 2 + h];
    }
    if (q8 == 0) {
#pragma unroll
        for (int nt = 0; nt < 8; nt++)
#pragma unroll
            for (int c = 0; c < 2; c++)
                sCol[wmf][wnf * 64 + nt * 8 + r4 * 2 + c] = cm[nt * 2 + c];
    }
    __syncthreads();
    if (tid < 128) {
        maxQp[((size_t)b * 4 + at) * QLn + tid] = fmaxf(sRow[0][tid], sRow[1][tid]);
        float m = fmaxf(fmaxf(sCol[0][tid], sCol[1][tid]), fmaxf(sCol[2][tid], sCol[3][tid]));
        maxA[(size_t)b * ALn + at * 128 + tid] = m;
    }
}

// ---------------- finalize ----------------
__device__ __forceinline__ float blkReduce(float v, bool domax) {
    __shared__ float sb[8];
#pragma unroll
    for (int o = 16; o; o >>= 1) {
        float ov = __shfl_xor_sync(0xffffffffu, v, o);
        v = domax ? fmaxf(v, ov) : v + ov;
    }
    __syncthreads();
    if ((threadIdx.x & 31) == 0) sb[threadIdx.x >> 5] = v;
    __syncthreads();
    float r = sb[0];
#pragma unroll
    for (int w = 1; w < 8; w++) r = domax ? fmaxf(r, sb[w]) : r + sb[w];
    return r;
}

__global__ void __launch_bounds__(256)
final_kernel(const float* __restrict__ Q, const float* __restrict__ A,
             const float* __restrict__ maxQp, const float* __restrict__ maxA,
             float* __restrict__ out) {
    __shared__ float roQ[QLn];
    __shared__ float roA[ALn];
    __shared__ float rQ[Fn];
    __shared__ float rA[Fn];
    const int b = blockIdx.x, tid = threadIdx.x;

    float v = -2.0f;
    if (tid < QLn) {
        const float* mp = maxQp + (size_t)b * 4 * QLn + tid;
        v = fmaxf(fmaxf(mp[0], mp[QLn]), fmaxf(mp[2 * QLn], mp[3 * QLn]));
    }
    float m = blkReduce(v, true);
    float e = (tid < QLn) ? __expf(v - m) : 0.0f;
    float s = blkReduce(e, false);
    if (tid < QLn) roQ[tid] = e / s;

    float v0 = maxA[(size_t)b * ALn + tid];
    float v1 = maxA[(size_t)b * ALn + 256 + tid];
    m = blkReduce(fmaxf(v0, v1), true);
    float e0 = __expf(v0 - m), e1 = __expf(v1 - m);
    s = blkReduce(e0 + e1, false);
    roA[tid] = e0 / s;
    roA[tid + 256] = e1 / s;
    __syncthreads();

    for (int f = tid; f < Fn; f += 256) {
        const float4* qr = (const float4*)(Q + ((size_t)b * Fn + f) * QLn);
        float a = 0.0f;
#pragma unroll 8
        for (int c = 0; c < QLn / 4; c++) {
            float4 qv = qr[c];
            const float* w = &roQ[c * 4];
            a += qv.x * w[0] + qv.y * w[1] + qv.z * w[2] + qv.w * w[3];
        }
        rQ[f] = a;
    }
    for (int f = tid; f < Fn; f += 256) {
        const float4* ar = (const float4*)(A + ((size_t)b * Fn + f) * ALn);
        float a = 0.0f;
#pragma unroll 8
        for (int c = 0; c < ALn / 4; c++) {
            float4 qv = ar[c];
            const float* w = &roA[c * 4];
            a += qv.x * w[0] + qv.y * w[1] + qv.z * w[2] + qv.w * w[3];
        }
        rA[f] = a;
    }
    __syncthreads();

    float d = 0.0f, qq = 0.0f, aa = 0.0f;
    for (int f = tid; f < Fn; f += 256) {
        float x = rQ[f], y = rA[f];
        d += x * y; qq += x * x; aa += y * y;
    }
    d = blkReduce(d, false);
    qq = blkReduce(qq, false);
    aa = blkReduce(aa, false);
    if (tid == 0)
        out[b] = d / (fmaxf(sqrtf(qq), 1e-8f) * fmaxf(sqrtf(aa), 1e-8f));
}

// ---------------- launch ----------------
extern "C" void kernel_launch(void* const* d_in, const int* in_sizes, int n_in,
                              void* d_out, int out_size) {
    const int*   question = (const int*)d_in[0];
    const int*   answer   = (const int*)d_in[1];
    const float* emb      = (const float*)d_in[2];
    const float* conv_w   = (const float*)d_in[3];
    const float* conv_b   = (const float*)d_in[4];
    const float* U        = (const float*)d_in[5];
    float* out = (float*)d_out;

    float *biasPad, *b2, *Ac, *Qc, *tQc, *maxQp, *maxA;
    __nv_bfloat16 *Whi, *Wlo, *W2hi, *W2lo, *eHi, *eLo;
    cudaGetSymbolAddress((void**)&biasPad, d_biasPad);
    cudaGetSymbolAddress((void**)&b2,      d_b2);
    cudaGetSymbolAddress((void**)&Whi,     d_Whi);
    cudaGetSymbolAddress((void**)&Wlo,     d_Wlo);
    cudaGetSymbolAddress((void**)&W2hi,    d_W2hi);
    cudaGetSymbolAddress((void**)&W2lo,    d_W2lo);
    cudaGetSymbolAddress((void**)&eHi,     d_embHi);
    cudaGetSymbolAddress((void**)&eLo,     d_embLo);
    cudaGetSymbolAddress((void**)&Ac,      d_A);
    cudaGetSymbolAddress((void**)&Qc,      d_Q);
    cudaGetSymbolAddress((void**)&tQc,     d_tQ);
    cudaGetSymbolAddress((void**)&maxQp,   d_maxQp);
    cudaGetSymbolAddress((void**)&maxA,    d_maxA);

    cudaFuncSetAttribute(conv_mma, cudaFuncAttributeMaxDynamicSharedMemorySize, SMEM_MMA);

    const int prepBlocks = (3 * Fp * EPW + 255) / 256;
    prep_w<<<prepBlocks, 256>>>(conv_w, conv_b, biasPad, Whi, Wlo);
    prep_w2<<<prepBlocks, 256>>>(U, conv_b, conv_w, b2, W2hi, W2lo);
    emb_cvt<<<(NEMBP + 255) / 256, 256>>>(emb, eHi, eLo);

    dim3 gA(ALn / 128, Fp / 128, Bn);
    conv_mma<<<gA, 256, SMEM_MMA>>>(answer, ALn, eHi, eLo, Whi, Wlo, biasPad, Ac);
    dim3 gQ(QLn / 128, Fp / 128, Bn);
    conv_mma<<<gQ, 256, SMEM_MMA>>>(question, QLn, eHi, eLo, Whi, Wlo, biasPad, Qc);
    conv_mma<<<gQ, 256, SMEM_MMA>>>(question, QLn, eHi, eLo, W2hi, W2lo, b2, tQc);

    dim3 gG(4, Bn);
    g_mma<<<gG, 256>>>(tQc, Ac, maxQp, maxA);
    final_kernel<<<Bn, 256>>>(Qc, Ac, maxQp, maxA, out);
}